// round 2
// baseline (speedup 1.0000x reference)
#include <cuda_runtime.h>
#include <cstdint>

#define D     64
#define NREL  32
#define MAXCAT 100000
#define MAXE   1600000

// ---- scratch (no allocations allowed) ----
__device__ float g_S[(size_t)MAXCAT * NREL];   // 12.8 MB: S[c,r] = sum_d cat[c,d]^2 * W[r,d]^2
__device__ float g_e[MAXE];                    // 6.4 MB: att -> exp values
__device__ float g_max[MAXCAT];
__device__ float g_sum[MAXCAT];

__device__ __forceinline__ void red_add_v4(float* addr, float4 v) {
    asm volatile("red.global.add.v4.f32 [%0], {%1,%2,%3,%4};"
                 :: "l"(addr), "f"(v.x), "f"(v.y), "f"(v.z), "f"(v.w)
                 : "memory");
}

// zero per-head softmax stats
__global__ void k_zero(int n) {
    int i = blockIdx.x * blockDim.x + threadIdx.x;
    if (i < n) { g_max[i] = 0.f; g_sum[i] = 0.f; }
}

// S[c,r] = sum_d cat[c,d]^2 * W[r,d]^2
__global__ void k_sq(const float* __restrict__ cat, const float* __restrict__ W, int n_cat) {
    __shared__ float sw[NREL * D];
    for (int i = threadIdx.x; i < NREL * D; i += blockDim.x) {
        float v = W[i]; sw[i] = v * v;
    }
    __syncthreads();
    int c = blockIdx.x * blockDim.x + threadIdx.x;
    if (c >= n_cat) return;
    const float4* row = reinterpret_cast<const float4*>(cat + (size_t)c * D);
    float c2[D];
#pragma unroll
    for (int i = 0; i < D / 4; i++) {
        float4 v = row[i];
        c2[4*i+0] = v.x*v.x; c2[4*i+1] = v.y*v.y;
        c2[4*i+2] = v.z*v.z; c2[4*i+3] = v.w*v.w;
    }
    float* out = g_S + (size_t)c * NREL;
#pragma unroll 4
    for (int r = 0; r < NREL; r++) {
        const float4* w4 = reinterpret_cast<const float4*>(sw + r * D);
        float acc = 0.f;
#pragma unroll
        for (int i = 0; i < D / 4; i++) {
            float4 w = w4[i];
            acc += c2[4*i+0]*w.x + c2[4*i+1]*w.y + c2[4*i+2]*w.z + c2[4*i+3]*w.w;
        }
        out[r] = acc;
    }
}

// att[e] = S[h,r] * S[t,r];  per-head max via int atomicMax (att >= 0)
__global__ void k_att(const int* __restrict__ head, const int* __restrict__ tail,
                      const int* __restrict__ et, int E) {
    int e = blockIdx.x * blockDim.x + threadIdx.x;
    if (e >= E) return;
    int h = head[e], t = tail[e], r = et[e] - 1;
    float a = g_S[(size_t)h * NREL + r] * g_S[(size_t)t * NREL + r];
    g_e[e] = a;
    atomicMax(reinterpret_cast<int*>(&g_max[h]), __float_as_int(a));
}

// e[e] = exp(att - max[h]);  per-head sum
__global__ void k_exp(const int* __restrict__ head, int E) {
    int e = blockIdx.x * blockDim.x + threadIdx.x;
    if (e >= E) return;
    int h = head[e];
    float v = __expf(g_e[e] - g_max[h]);
    g_e[e] = v;
    atomicAdd(&g_sum[h], v);
}

// category_agg[h] += (e/sum[h]) * cat[t] * W[r]   (8 threads per edge, red.v4)
__global__ void k_scat(const float* __restrict__ cat, const float* __restrict__ W,
                       const int* __restrict__ head, const int* __restrict__ tail,
                       const int* __restrict__ et, float* __restrict__ agg, int E) {
    __shared__ float sw[NREL * D];
    for (int i = threadIdx.x; i < NREL * D; i += blockDim.x) sw[i] = W[i];
    __syncthreads();
    int idx = blockIdx.x * blockDim.x + threadIdx.x;
    int e = idx >> 3, sub = idx & 7;
    if (e >= E) return;
    int h = head[e], t = tail[e], r = et[e] - 1;
    float wgt = g_e[e] / g_sum[h];
    const float4* crow = reinterpret_cast<const float4*>(cat + (size_t)t * D) + sub * 2;
    const float4* wrow = reinterpret_cast<const float4*>(sw + r * D) + sub * 2;
    float* dst = agg + (size_t)h * D + sub * 8;
    float4 c0 = crow[0], c1 = crow[1];
    float4 w0 = wrow[0], w1 = wrow[1];
    float4 v0 = make_float4(wgt*c0.x*w0.x, wgt*c0.y*w0.y, wgt*c0.z*w0.z, wgt*c0.w*w0.w);
    float4 v1 = make_float4(wgt*c1.x*w1.x, wgt*c1.y*w1.y, wgt*c1.z*w1.z, wgt*c1.w*w1.w);
    red_add_v4(dst, v0);
    red_add_v4(dst + 4, v1);
}

// user_agg[row] += val * cat[col]   (8 threads per nnz, red.v4)
__global__ void k_uscat(const float* __restrict__ cat,
                        const int* __restrict__ rows, const int* __restrict__ cols,
                        const float* __restrict__ vals, float* __restrict__ uagg, int nnz) {
    int idx = blockIdx.x * blockDim.x + threadIdx.x;
    int i = idx >> 3, sub = idx & 7;
    if (i >= nnz) return;
    int rr = rows[i], cc = cols[i];
    float v = vals[i];
    const float4* crow = reinterpret_cast<const float4*>(cat + (size_t)cc * D) + sub * 2;
    float* dst = uagg + (size_t)rr * D + sub * 8;
    float4 c0 = crow[0], c1 = crow[1];
    float4 v0 = make_float4(v*c0.x, v*c0.y, v*c0.z, v*c0.w);
    float4 v1 = make_float4(v*c1.x, v*c1.y, v*c1.z, v*c1.w);
    red_add_v4(dst, v0);
    red_add_v4(dst + 4, v1);
}

// user epilogue: score = softmax(u @ W^T); ua *= (1 + score @ W)   (warp per user)
__global__ void k_user(const float* __restrict__ ue, const float* __restrict__ W,
                       float* __restrict__ ua, int n_users) {
    __shared__ float sw[NREL * D];     // row-major W
    __shared__ float swT[D * NREL];    // transposed W for conflict-free logit loop
    __shared__ float su[8][D];
    for (int i = threadIdx.x; i < NREL * D; i += blockDim.x) {
        float v = W[i];
        sw[i] = v;
        int r = i / D, d = i % D;
        swT[d * NREL + r] = v;
    }
    __syncthreads();
    int warp = threadIdx.x >> 5, lane = threadIdx.x & 31;
    int u = blockIdx.x * 8 + warp;
    if (u >= n_users) return;
    su[warp][lane]      = ue[(size_t)u * D + lane];
    su[warp][lane + 32] = ue[(size_t)u * D + lane + 32];
    __syncwarp();
    // logit for relation `lane`
    float acc = 0.f;
#pragma unroll
    for (int d = 0; d < D; d++) acc += su[warp][d] * swT[d * NREL + lane];
    // warp softmax over 32 relations
    float m = acc;
#pragma unroll
    for (int o = 16; o > 0; o >>= 1) m = fmaxf(m, __shfl_xor_sync(0xffffffffu, m, o));
    float p = __expf(acc - m);
    float s = p;
#pragma unroll
    for (int o = 16; o > 0; o >>= 1) s += __shfl_xor_sync(0xffffffffu, s, o);
    p /= s;
    // comb[d] = sum_r p[r] * W[r,d]; each lane handles d = lane, lane+32
    float c0 = 0.f, c1 = 0.f;
#pragma unroll
    for (int r = 0; r < NREL; r++) {
        float pr = __shfl_sync(0xffffffffu, p, r);
        c0 += pr * sw[r * D + lane];
        c1 += pr * sw[r * D + lane + 32];
    }
    float a0 = ua[(size_t)u * D + lane];
    float a1 = ua[(size_t)u * D + lane + 32];
    ua[(size_t)u * D + lane]      = a0 * (1.f + c0);
    ua[(size_t)u * D + lane + 32] = a1 * (1.f + c1);
}

extern "C" void kernel_launch(void* const* d_in, const int* in_sizes, int n_in,
                              void* d_out, int out_size) {
    const float* cat = (const float*)d_in[0];
    const float* ue  = (const float*)d_in[1];
    const int*   ei  = (const int*)d_in[2];     // int32 (JAX x64 disabled)
    const int*   et  = (const int*)d_in[3];
    const int*   ir  = (const int*)d_in[4];
    const int*   ic  = (const int*)d_in[5];
    const float* iv  = (const float*)d_in[6];
    const float* W   = (const float*)d_in[7];

    int n_cat   = in_sizes[0] / D;
    int n_users = in_sizes[1] / D;
    int E       = in_sizes[3];
    int nnz     = in_sizes[6];

    const int* head = ei;
    const int* tail = ei + E;

    float* cat_agg  = (float*)d_out;
    float* user_agg = (float*)d_out + (size_t)n_cat * D;

    cudaMemsetAsync(d_out, 0, (size_t)out_size * sizeof(float));
    k_zero<<<(n_cat + 255) / 256, 256>>>(n_cat);
    k_sq<<<(n_cat + 127) / 128, 128>>>(cat, W, n_cat);
    k_att<<<(E + 255) / 256, 256>>>(head, tail, et, E);
    k_exp<<<(E + 255) / 256, 256>>>(head, E);
    {
        long long thr = (long long)E * 8;
        k_scat<<<(int)((thr + 255) / 256), 256>>>(cat, W, head, tail, et, cat_agg, E);
    }
    {
        long long thr = (long long)nnz * 8;
        k_uscat<<<(int)((thr + 255) / 256), 256>>>(cat, ir, ic, iv, user_agg, nnz);
    }
    k_user<<<(n_users + 7) / 8, 256>>>(ue, W, user_agg, n_users);
}

// round 3
// speedup vs baseline: 1.2689x; 1.2689x over previous
#include <cuda_runtime.h>
#include <cstdint>

#define D     64
#define NREL  32
#define MAXCAT  100000
#define MAXUSER 50000
#define MAXE    1600000
#define MAXNNZ  1000000
#define FULL 0xffffffffu

// ---- scratch ----
__device__ float g_S[(size_t)MAXCAT * NREL];     // S[c,r] = sum_d cat[c,d]^2 * W[r,d]^2
__device__ int   g_cnt_e[MAXCAT + 1];
__device__ int   g_off_e[MAXCAT + 1];
__device__ int   g_pos_e[MAXCAT];
__device__ int   g_bsum_e[128];
__device__ int   g_pk[MAXE];                     // tail | rel<<17
__device__ int   g_cnt_u[MAXUSER + 1];
__device__ int   g_off_u[MAXUSER + 1];
__device__ int   g_pos_u[MAXUSER];
__device__ int   g_bsum_u[128];
__device__ int   g_uc[MAXNNZ];
__device__ float g_uv[MAXNNZ];

// zero histograms
__global__ void k_zero(int n_cat, int n_users) {
    int i = blockIdx.x * blockDim.x + threadIdx.x;
    if (i <= n_cat)   g_cnt_e[i] = 0;
    if (i <= n_users) g_cnt_u[i] = 0;
}

// S[c,r] = sum_d cat[c,d]^2 * W[r,d]^2
__global__ void k_sq(const float* __restrict__ cat, const float* __restrict__ W, int n_cat) {
    __shared__ float sw[NREL * D];
    for (int i = threadIdx.x; i < NREL * D; i += blockDim.x) { float v = W[i]; sw[i] = v * v; }
    __syncthreads();
    int c = blockIdx.x * blockDim.x + threadIdx.x;
    if (c >= n_cat) return;
    const float4* row = reinterpret_cast<const float4*>(cat + (size_t)c * D);
    float c2[D];
#pragma unroll
    for (int i = 0; i < D / 4; i++) {
        float4 v = row[i];
        c2[4*i+0] = v.x*v.x; c2[4*i+1] = v.y*v.y; c2[4*i+2] = v.z*v.z; c2[4*i+3] = v.w*v.w;
    }
    float* out = g_S + (size_t)c * NREL;
#pragma unroll 4
    for (int r = 0; r < NREL; r++) {
        const float4* w4 = reinterpret_cast<const float4*>(sw + r * D);
        float acc = 0.f;
#pragma unroll
        for (int i = 0; i < D / 4; i++) {
            float4 w = w4[i];
            acc += c2[4*i+0]*w.x + c2[4*i+1]*w.y + c2[4*i+2]*w.z + c2[4*i+3]*w.w;
        }
        out[r] = acc;
    }
}

// histogram heads and user rows in one launch
__global__ void k_hist(const int* __restrict__ head, const int* __restrict__ irow,
                       int E, int nnz) {
    int i = blockIdx.x * blockDim.x + threadIdx.x;
    if (i < E) atomicAdd(&g_cnt_e[head[i]], 1);
    else { int j = i - E; if (j < nnz) atomicAdd(&g_cnt_u[irow[j]], 1); }
}

// --- multi-block exclusive scan ---
__global__ void k_scanA(const int* __restrict__ cnt, int* __restrict__ off,
                        int* __restrict__ bsum, int n) {
    __shared__ int s[1024];
    int tid = threadIdx.x;
    int i = blockIdx.x * 1024 + tid;
    int v = (i < n) ? cnt[i] : 0;
    s[tid] = v; __syncthreads();
    for (int o = 1; o < 1024; o <<= 1) {
        int t = (tid >= o) ? s[tid - o] : 0;
        __syncthreads();
        s[tid] += t;
        __syncthreads();
    }
    if (i < n) off[i] = s[tid] - v;       // exclusive within chunk
    if (tid == 1023) bsum[blockIdx.x] = s[1023];
}

__global__ void k_scanB(int* __restrict__ bsum, int* __restrict__ off, int nb, int n) {
    __shared__ int s[128];
    int tid = threadIdx.x;
    int v = (tid < nb) ? bsum[tid] : 0;
    s[tid] = v; __syncthreads();
    for (int o = 1; o < 128; o <<= 1) {
        int t = (tid >= o) ? s[tid - o] : 0;
        __syncthreads();
        s[tid] += t;
        __syncthreads();
    }
    if (tid < nb) bsum[tid] = s[tid] - v;  // exclusive block offsets
    if (tid == 127) off[n] = s[127];       // grand total
}

__global__ void k_scanC(int* __restrict__ off, int* __restrict__ pos,
                        const int* __restrict__ bsum, int n) {
    int i = blockIdx.x * 1024 + threadIdx.x;
    if (i < n) {
        int o = off[i] + bsum[blockIdx.x];
        off[i] = o;
        pos[i] = o;
    }
}

// bucket-scatter edges and nnz entries
__global__ void k_sort(const int* __restrict__ head, const int* __restrict__ tail,
                       const int* __restrict__ et,
                       const int* __restrict__ irow, const int* __restrict__ icol,
                       const float* __restrict__ ival, int E, int nnz) {
    int i = blockIdx.x * blockDim.x + threadIdx.x;
    if (i < E) {
        int h = head[i];
        int p = atomicAdd(&g_pos_e[h], 1);
        g_pk[p] = tail[i] | ((et[i] - 1) << 17);
    } else {
        int j = i - E;
        if (j < nnz) {
            int r = irow[j];
            int p = atomicAdd(&g_pos_u[r], 1);
            g_uc[p] = icol[j];
            g_uv[p] = ival[j];
        }
    }
}

// fused per-head: att -> softmax -> weighted aggregation. Warp per head, no atomics.
__global__ void __launch_bounds__(256) k_agg(const float* __restrict__ cat,
                                             const float* __restrict__ W,
                                             float* __restrict__ agg, int n_cat) {
    __shared__ float sw[NREL * D];
    for (int i = threadIdx.x; i < NREL * D; i += blockDim.x) sw[i] = W[i];
    __syncthreads();
    int warp = threadIdx.x >> 5, lane = threadIdx.x & 31;
    int h = blockIdx.x * 8 + warp;
    if (h >= n_cat) return;
    int beg = g_off_e[h], end = g_off_e[h + 1];
    float Sh = g_S[(size_t)h * NREL + lane];   // lane r holds S[h,r]

    // pass 1: segment max (att >= 0 so 0 is a safe identity)
    float m = 0.f;
    for (int b = beg; b < end; b += 32) {
        int i = b + lane;
        bool val = i < end;
        int pk = val ? g_pk[i] : 0;
        int t = pk & 0x1FFFF, r = pk >> 17;
        float shr = __shfl_sync(FULL, Sh, r);
        float st = val ? g_S[(size_t)t * NREL + r] : 0.f;
        float a = shr * st;
        if (val) m = fmaxf(m, a);
    }
#pragma unroll
    for (int o = 16; o > 0; o >>= 1) m = fmaxf(m, __shfl_xor_sync(FULL, m, o));

    // pass 2: exp, sum, weighted accumulation
    float sum = 0.f, acc0 = 0.f, acc1 = 0.f;
    for (int b = beg; b < end; b += 32) {
        int i = b + lane;
        bool val = i < end;
        int pk = val ? g_pk[i] : 0;
        int t = pk & 0x1FFFF, r = pk >> 17;
        float shr = __shfl_sync(FULL, Sh, r);
        float st = val ? g_S[(size_t)t * NREL + r] : 0.f;
        float e = val ? __expf(shr * st - m) : 0.f;
        sum += e;
        int cnt = min(32, end - b);
        for (int j = 0; j < cnt; j++) {
            float ej = __shfl_sync(FULL, e, j);
            int tj = __shfl_sync(FULL, t, j);
            int rj = __shfl_sync(FULL, r, j);
            const float* cr = cat + (size_t)tj * D;
            acc0 += ej * cr[lane]      * sw[rj * D + lane];
            acc1 += ej * cr[lane + 32] * sw[rj * D + lane + 32];
        }
    }
#pragma unroll
    for (int o = 16; o > 0; o >>= 1) sum += __shfl_xor_sync(FULL, sum, o);
    float inv = (end > beg) ? 1.f / sum : 0.f;
    agg[(size_t)h * D + lane]      = acc0 * inv;
    agg[(size_t)h * D + 32 + lane] = acc1 * inv;
}

// fused per-user: SpMM row + softmax gating epilogue. Warp per user, no atomics.
__global__ void __launch_bounds__(256) k_uagg(const float* __restrict__ cat,
                                              const float* __restrict__ ue,
                                              const float* __restrict__ W,
                                              float* __restrict__ ua, int n_users) {
    __shared__ float sw[NREL * D];      // W row-major
    __shared__ float swT[D * NREL];     // swT[d*32+r] = W[r,d]
    for (int i = threadIdx.x; i < NREL * D; i += blockDim.x) {
        float v = W[i];
        sw[i] = v;
        int r = i / D, d = i % D;
        swT[d * NREL + r] = v;
    }
    __syncthreads();
    int warp = threadIdx.x >> 5, lane = threadIdx.x & 31;
    int u = blockIdx.x * 8 + warp;
    if (u >= n_users) return;
    int beg = g_off_u[u], end = g_off_u[u + 1];

    float acc0 = 0.f, acc1 = 0.f;
    for (int b = beg; b < end; b += 32) {
        int i = b + lane;
        bool val = i < end;
        int c = val ? g_uc[i] : 0;
        float v = val ? g_uv[i] : 0.f;
        int cnt = min(32, end - b);
        for (int j = 0; j < cnt; j++) {
            int cj = __shfl_sync(FULL, c, j);
            float vj = __shfl_sync(FULL, v, j);
            const float* cr = cat + (size_t)cj * D;
            acc0 += vj * cr[lane];
            acc1 += vj * cr[lane + 32];
        }
    }

    // gating: score = softmax(ue[u] @ W^T); out = acc * (1 + score @ W)
    float u0 = ue[(size_t)u * D + lane];
    float u1 = ue[(size_t)u * D + 32 + lane];
    float logit = 0.f;
#pragma unroll
    for (int d = 0; d < 32; d++) {
        float ud = __shfl_sync(FULL, u0, d);
        logit += ud * swT[d * NREL + lane];
    }
#pragma unroll
    for (int d = 0; d < 32; d++) {
        float ud = __shfl_sync(FULL, u1, d);
        logit += ud * swT[(d + 32) * NREL + lane];
    }
    float mm = logit;
#pragma unroll
    for (int o = 16; o > 0; o >>= 1) mm = fmaxf(mm, __shfl_xor_sync(FULL, mm, o));
    float p = __expf(logit - mm);
    float s = p;
#pragma unroll
    for (int o = 16; o > 0; o >>= 1) s += __shfl_xor_sync(FULL, s, o);
    p /= s;
    float c0 = 0.f, c1 = 0.f;
#pragma unroll
    for (int r = 0; r < NREL; r++) {
        float pr = __shfl_sync(FULL, p, r);
        c0 += pr * sw[r * D + lane];
        c1 += pr * sw[r * D + lane + 32];
    }
    ua[(size_t)u * D + lane]      = acc0 * (1.f + c0);
    ua[(size_t)u * D + 32 + lane] = acc1 * (1.f + c1);
}

extern "C" void kernel_launch(void* const* d_in, const int* in_sizes, int n_in,
                              void* d_out, int out_size) {
    const float* cat = (const float*)d_in[0];
    const float* ue  = (const float*)d_in[1];
    const int*   ei  = (const int*)d_in[2];
    const int*   et  = (const int*)d_in[3];
    const int*   ir  = (const int*)d_in[4];
    const int*   ic  = (const int*)d_in[5];
    const float* iv  = (const float*)d_in[6];
    const float* W   = (const float*)d_in[7];

    int n_cat   = in_sizes[0] / D;
    int n_users = in_sizes[1] / D;
    int E       = in_sizes[3];
    int nnz     = in_sizes[6];

    const int* head = ei;
    const int* tail = ei + E;

    float* cat_agg  = (float*)d_out;
    float* user_agg = (float*)d_out + (size_t)n_cat * D;

    int nmax = (n_cat > n_users ? n_cat : n_users) + 1;
    int tot  = E + nnz;
    int nbe  = (n_cat + 1023) / 1024;
    int nbu  = (n_users + 1023) / 1024;

    int* off_e; cudaGetSymbolAddress((void**)&off_e, g_off_e);
    int* cnt_e; cudaGetSymbolAddress((void**)&cnt_e, g_cnt_e);
    int* pos_e; cudaGetSymbolAddress((void**)&pos_e, g_pos_e);
    int* bse;   cudaGetSymbolAddress((void**)&bse, g_bsum_e);
    int* off_u; cudaGetSymbolAddress((void**)&off_u, g_off_u);
    int* cnt_u; cudaGetSymbolAddress((void**)&cnt_u, g_cnt_u);
    int* pos_u; cudaGetSymbolAddress((void**)&pos_u, g_pos_u);
    int* bsu;   cudaGetSymbolAddress((void**)&bsu, g_bsum_u);

    k_zero<<<(nmax + 255) / 256, 256>>>(n_cat, n_users);
    k_sq<<<(n_cat + 127) / 128, 128>>>(cat, W, n_cat);
    k_hist<<<(tot + 255) / 256, 256>>>(head, ir, E, nnz);
    k_scanA<<<nbe, 1024>>>(cnt_e, off_e, bse, n_cat);
    k_scanB<<<1, 128>>>(bse, off_e, nbe, n_cat);
    k_scanC<<<nbe, 1024>>>(off_e, pos_e, bse, n_cat);
    k_scanA<<<nbu, 1024>>>(cnt_u, off_u, bsu, n_users);
    k_scanB<<<1, 128>>>(bsu, off_u, nbu, n_users);
    k_scanC<<<nbu, 1024>>>(off_u, pos_u, bsu, n_users);
    k_sort<<<(tot + 255) / 256, 256>>>(head, tail, et, ir, ic, iv, E, nnz);
    k_agg<<<(n_cat + 7) / 8, 256>>>(cat, W, cat_agg, n_cat);
    k_uagg<<<(n_users + 7) / 8, 256>>>(cat, ue, W, user_agg, n_users);
}

// round 4
// speedup vs baseline: 1.2720x; 1.0024x over previous
#include <cuda_runtime.h>
#include <cstdint>

#define D     64
#define NREL  32
#define MAXCAT  100000
#define MAXUSER 50000
#define MAXE    1600000
#define MAXNNZ  1000000
#define FULL 0xffffffffu

// ---- scratch ----
__device__ float g_S[(size_t)MAXCAT * NREL];       // S[c,r] = sum_d cat[c,d]^2 * W[r,d]^2
__device__ int   g_cnt[MAXCAT + MAXUSER + 2];      // combined histogram: [heads | user rows]
__device__ int   g_off[MAXCAT + MAXUSER + 2];      // combined exclusive scan
__device__ int   g_pos[MAXCAT + MAXUSER + 2];      // scatter cursors
__device__ int   g_bsum[256];
__device__ int   g_pk[MAXE];                       // tail | rel<<17, bucketed by head
__device__ int   g_uc[MAXNNZ];                     // cols bucketed by user row
__device__ float g_uv[MAXNNZ];

__global__ void k_zero(int n_tot) {
    int i = blockIdx.x * blockDim.x + threadIdx.x;
    if (i <= n_tot) g_cnt[i] = 0;
}

// S[c,r] = sum_d cat[c,d]^2 * W[r,d]^2
__global__ void k_sq(const float* __restrict__ cat, const float* __restrict__ W, int n_cat) {
    __shared__ float sw[NREL * D];
    for (int i = threadIdx.x; i < NREL * D; i += blockDim.x) { float v = W[i]; sw[i] = v * v; }
    __syncthreads();
    int c = blockIdx.x * blockDim.x + threadIdx.x;
    if (c >= n_cat) return;
    const float4* row = reinterpret_cast<const float4*>(cat + (size_t)c * D);
    float c2[D];
#pragma unroll
    for (int i = 0; i < D / 4; i++) {
        float4 v = row[i];
        c2[4*i+0] = v.x*v.x; c2[4*i+1] = v.y*v.y; c2[4*i+2] = v.z*v.z; c2[4*i+3] = v.w*v.w;
    }
    float* out = g_S + (size_t)c * NREL;
#pragma unroll 4
    for (int r = 0; r < NREL; r++) {
        const float4* w4 = reinterpret_cast<const float4*>(sw + r * D);
        float acc = 0.f;
#pragma unroll
        for (int i = 0; i < D / 4; i++) {
            float4 w = w4[i];
            acc += c2[4*i+0]*w.x + c2[4*i+1]*w.y + c2[4*i+2]*w.z + c2[4*i+3]*w.w;
        }
        out[r] = acc;
    }
}

// combined histogram: heads at [0,n_cat), user rows at [n_cat, n_cat+n_users)
__global__ void k_hist(const int* __restrict__ head, const int* __restrict__ irow,
                       int E, int nnz, int n_cat) {
    int i = blockIdx.x * blockDim.x + threadIdx.x;
    if (i < E) atomicAdd(&g_cnt[head[i]], 1);
    else { int j = i - E; if (j < nnz) atomicAdd(&g_cnt[n_cat + irow[j]], 1); }
}

// --- multi-block exclusive scan over combined histogram ---
__global__ void k_scanA(int n) {
    __shared__ int s[1024];
    int tid = threadIdx.x;
    int i = blockIdx.x * 1024 + tid;
    int v = (i < n) ? g_cnt[i] : 0;
    s[tid] = v; __syncthreads();
    for (int o = 1; o < 1024; o <<= 1) {
        int t = (tid >= o) ? s[tid - o] : 0;
        __syncthreads();
        s[tid] += t;
        __syncthreads();
    }
    if (i < n) g_off[i] = s[tid] - v;
    if (tid == 1023) g_bsum[blockIdx.x] = s[1023];
}

__global__ void k_scanB(int nb, int n) {
    __shared__ int s[256];
    int tid = threadIdx.x;
    int v = (tid < nb) ? g_bsum[tid] : 0;
    s[tid] = v; __syncthreads();
    for (int o = 1; o < 256; o <<= 1) {
        int t = (tid >= o) ? s[tid - o] : 0;
        __syncthreads();
        s[tid] += t;
        __syncthreads();
    }
    if (tid < nb) g_bsum[tid] = s[tid] - v;
    if (tid == 255) g_off[n] = s[255];
}

__global__ void k_scanC(int n) {
    int i = blockIdx.x * 1024 + threadIdx.x;
    if (i < n) {
        int o = g_off[i] + g_bsum[blockIdx.x];
        g_off[i] = o;
        g_pos[i] = o;
    }
}

// bucket-scatter edges and nnz entries (user positions are offset by E globally)
__global__ void k_sort(const int* __restrict__ head, const int* __restrict__ tail,
                       const int* __restrict__ et,
                       const int* __restrict__ irow, const int* __restrict__ icol,
                       const float* __restrict__ ival, int E, int nnz, int n_cat) {
    int i = blockIdx.x * blockDim.x + threadIdx.x;
    if (i < E) {
        int h = head[i];
        int p = atomicAdd(&g_pos[h], 1);
        g_pk[p] = tail[i] | ((et[i] - 1) << 17);
    } else {
        int j = i - E;
        if (j < nnz) {
            int r = irow[j];
            int p = atomicAdd(&g_pos[n_cat + r], 1) - E;
            g_uc[p] = icol[j];
            g_uv[p] = ival[j];
        }
    }
}

// fused per-head: att -> softmax -> weighted aggregation. Warp per head, no atomics.
__global__ void __launch_bounds__(256) k_agg(const float* __restrict__ cat,
                                             const float* __restrict__ W,
                                             float* __restrict__ agg, int n_cat) {
    __shared__ float sw[NREL * D];
    for (int i = threadIdx.x; i < NREL * D; i += blockDim.x) sw[i] = W[i];
    __syncthreads();
    int warp = threadIdx.x >> 5, lane = threadIdx.x & 31;
    int h = blockIdx.x * 8 + warp;
    if (h >= n_cat) return;
    int beg = g_off[h], end = g_off[h + 1], len = end - beg;
    float* dst = agg + (size_t)h * D;
    if (len == 0) { dst[lane] = 0.f; dst[lane + 32] = 0.f; return; }

    float Sh = g_S[(size_t)h * NREL + lane];   // lane r holds S[h,r]
    float sum = 0.f, acc0 = 0.f, acc1 = 0.f;

    if (len <= 32) {
        // fast path: one batch, pk/S kept in registers across both passes
        bool val = lane < len;
        int pk = val ? g_pk[beg + lane] : 0;
        int t = val ? (pk & 0x1FFFF) : 0;
        int r = val ? (pk >> 17) : 0;
        float shr = __shfl_sync(FULL, Sh, r);
        float a = val ? shr * g_S[(size_t)t * NREL + r] : 0.f;  // att >= 0
        float m = a;
#pragma unroll
        for (int o = 16; o > 0; o >>= 1) m = fmaxf(m, __shfl_xor_sync(FULL, m, o));
        float e = val ? __expf(a - m) : 0.f;
        sum = e;
#pragma unroll
        for (int o = 16; o > 0; o >>= 1) sum += __shfl_xor_sync(FULL, sum, o);
        int lenUp = (len + 3) & ~3;      // padded lanes: e=0, t=0 -> harmless
        for (int j = 0; j < lenUp; j += 4) {
#pragma unroll
            for (int q = 0; q < 4; q++) {
                float ej = __shfl_sync(FULL, e, j + q);
                int tj = __shfl_sync(FULL, t, j + q);
                int rj = __shfl_sync(FULL, r, j + q);
                const float* cr = cat + (size_t)tj * D;
                acc0 += ej * cr[lane]      * sw[rj * D + lane];
                acc1 += ej * cr[lane + 32] * sw[rj * D + lane + 32];
            }
        }
    } else {
        // pass 1: segment max
        float m = 0.f;
        for (int b = beg; b < end; b += 32) {
            int i = b + lane;
            if (i < end) {
                int pk = g_pk[i];
                int t = pk & 0x1FFFF, r = pk >> 17;
                float shr = __shfl_sync(FULL, Sh, r);
                m = fmaxf(m, shr * g_S[(size_t)t * NREL + r]);
            } else {
                __shfl_sync(FULL, Sh, 0);   // keep shfl convergent
            }
        }
#pragma unroll
        for (int o = 16; o > 0; o >>= 1) m = fmaxf(m, __shfl_xor_sync(FULL, m, o));
        // pass 2: exp + accumulate, unrolled inner loop with zero-padding
        for (int b = beg; b < end; b += 32) {
            int i = b + lane;
            bool val = i < end;
            int pk = val ? g_pk[i] : 0;
            int t = val ? (pk & 0x1FFFF) : 0;
            int r = val ? (pk >> 17) : 0;
            float shr = __shfl_sync(FULL, Sh, r);
            float e = val ? __expf(shr * g_S[(size_t)t * NREL + r] - m) : 0.f;
            sum += e;
            int cnt = min(32, end - b);
            int cntUp = (cnt + 3) & ~3;
            for (int j = 0; j < cntUp; j += 4) {
#pragma unroll
                for (int q = 0; q < 4; q++) {
                    float ej = __shfl_sync(FULL, e, j + q);
                    int tj = __shfl_sync(FULL, t, j + q);
                    int rj = __shfl_sync(FULL, r, j + q);
                    const float* cr = cat + (size_t)tj * D;
                    acc0 += ej * cr[lane]      * sw[rj * D + lane];
                    acc1 += ej * cr[lane + 32] * sw[rj * D + lane + 32];
                }
            }
        }
#pragma unroll
        for (int o = 16; o > 0; o >>= 1) sum += __shfl_xor_sync(FULL, sum, o);
    }
    float inv = 1.f / sum;
    dst[lane]      = acc0 * inv;
    dst[lane + 32] = acc1 * inv;
}

// fused per-user: SpMM row + softmax gating epilogue. Warp per user, no atomics.
__global__ void __launch_bounds__(256) k_uagg(const float* __restrict__ cat,
                                              const float* __restrict__ ue,
                                              const float* __restrict__ W,
                                              float* __restrict__ ua,
                                              int n_users, int n_cat, int E) {
    __shared__ float sw[NREL * D];      // W row-major
    __shared__ float swT[D * NREL];     // swT[d*32+r] = W[r,d]
    for (int i = threadIdx.x; i < NREL * D; i += blockDim.x) {
        float v = W[i];
        sw[i] = v;
        int r = i / D, d = i % D;
        swT[d * NREL + r] = v;
    }
    __syncthreads();
    int warp = threadIdx.x >> 5, lane = threadIdx.x & 31;
    int u = blockIdx.x * 8 + warp;
    if (u >= n_users) return;
    int beg = g_off[n_cat + u] - E, end = g_off[n_cat + u + 1] - E;

    float acc0 = 0.f, acc1 = 0.f;
    for (int b = beg; b < end; b += 32) {
        int i = b + lane;
        bool val = i < end;
        int c = val ? g_uc[i] : 0;
        float v = val ? g_uv[i] : 0.f;
        int cnt = min(32, end - b);
        int cntUp = (cnt + 3) & ~3;
        for (int j = 0; j < cntUp; j += 4) {
#pragma unroll
            for (int q = 0; q < 4; q++) {
                int cj = __shfl_sync(FULL, c, j + q);
                float vj = __shfl_sync(FULL, v, j + q);
                const float* cr = cat + (size_t)cj * D;
                acc0 += vj * cr[lane];
                acc1 += vj * cr[lane + 32];
            }
        }
    }

    // gating: score = softmax(ue[u] @ W^T); out = acc * (1 + score @ W)
    float u0 = ue[(size_t)u * D + lane];
    float u1 = ue[(size_t)u * D + 32 + lane];
    float logit = 0.f;
#pragma unroll
    for (int d = 0; d < 32; d++) {
        float ud = __shfl_sync(FULL, u0, d);
        logit += ud * swT[d * NREL + lane];
    }
#pragma unroll
    for (int d = 0; d < 32; d++) {
        float ud = __shfl_sync(FULL, u1, d);
        logit += ud * swT[(d + 32) * NREL + lane];
    }
    float mm = logit;
#pragma unroll
    for (int o = 16; o > 0; o >>= 1) mm = fmaxf(mm, __shfl_xor_sync(FULL, mm, o));
    float p = __expf(logit - mm);
    float s = p;
#pragma unroll
    for (int o = 16; o > 0; o >>= 1) s += __shfl_xor_sync(FULL, s, o);
    p /= s;
    float c0 = 0.f, c1 = 0.f;
#pragma unroll
    for (int r = 0; r < NREL; r++) {
        float pr = __shfl_sync(FULL, p, r);
        c0 += pr * sw[r * D + lane];
        c1 += pr * sw[r * D + lane + 32];
    }
    ua[(size_t)u * D + lane]      = acc0 * (1.f + c0);
    ua[(size_t)u * D + 32 + lane] = acc1 * (1.f + c1);
}

extern "C" void kernel_launch(void* const* d_in, const int* in_sizes, int n_in,
                              void* d_out, int out_size) {
    const float* cat = (const float*)d_in[0];
    const float* ue  = (const float*)d_in[1];
    const int*   ei  = (const int*)d_in[2];
    const int*   et  = (const int*)d_in[3];
    const int*   ir  = (const int*)d_in[4];
    const int*   ic  = (const int*)d_in[5];
    const float* iv  = (const float*)d_in[6];
    const float* W   = (const float*)d_in[7];

    int n_cat   = in_sizes[0] / D;
    int n_users = in_sizes[1] / D;
    int E       = in_sizes[3];
    int nnz     = in_sizes[6];

    const int* head = ei;
    const int* tail = ei + E;

    float* cat_agg  = (float*)d_out;
    float* user_agg = (float*)d_out + (size_t)n_cat * D;

    int n_tot = n_cat + n_users;
    int tot   = E + nnz;
    int nb    = (n_tot + 1023) / 1024;

    k_zero<<<(n_tot + 256) / 256, 256>>>(n_tot);
    k_sq<<<(n_cat + 127) / 128, 128>>>(cat, W, n_cat);
    k_hist<<<(tot + 255) / 256, 256>>>(head, ir, E, nnz, n_cat);
    k_scanA<<<nb, 1024>>>(n_tot);
    k_scanB<<<1, 256>>>(nb, n_tot);
    k_scanC<<<nb, 1024>>>(n_tot);
    k_sort<<<(tot + 255) / 256, 256>>>(head, tail, et, ir, ic, iv, E, nnz, n_cat);
    k_agg<<<(n_cat + 7) / 8, 256>>>(cat, W, cat_agg, n_cat);
    k_uagg<<<(n_users + 7) / 8, 256>>>(cat, ue, W, user_agg, n_users, n_cat, E);
}

// round 5
// speedup vs baseline: 1.4387x; 1.1310x over previous
#include <cuda_runtime.h>
#include <cstdint>

#define D     64
#define NREL  32
#define MAXCAT  100000
#define MAXUSER 50000
#define MAXE    1600000
#define MAXNNZ  1000000
#define FULL 0xffffffffu

#define MULX2(o,a,b)   asm("mul.rn.f32x2 %0,%1,%2;"    : "=l"(o) : "l"(a), "l"(b))
#define FMAX2(o,a,b,c) asm("fma.rn.f32x2 %0,%1,%2,%3;" : "=l"(o) : "l"(a), "l"(b), "l"(c))
#define PACK2(o,x)     asm("mov.b64 %0,{%1,%1};"       : "=l"(o) : "f"(x))
#define UNPK2(x,y,i)   asm("mov.b64 {%0,%1},%2;"       : "=f"(x), "=f"(y) : "l"(i))

// ---- scratch ----
__device__ float g_S[(size_t)MAXCAT * NREL];
__device__ int   g_cnt[MAXCAT + MAXUSER + 2];
__device__ int   g_off[MAXCAT + MAXUSER + 2];
__device__ int   g_pos[MAXCAT + MAXUSER + 2];
__device__ int   g_bsum[256];
__device__ int   g_pk[MAXE];                       // tail | rel<<17, bucketed by head
__device__ int   g_uc[MAXNNZ];
__device__ float g_uv[MAXNNZ];

// fused: blocks [0,Z) zero the histogram; blocks [Z,Z+SQ) compute S
__global__ void k_front(const float* __restrict__ cat, const float* __restrict__ W,
                        int n_cat, int n_tot, int Z) {
    if ((int)blockIdx.x < Z) {
        int i = blockIdx.x * 256 + threadIdx.x;
        if (i <= n_tot) g_cnt[i] = 0;
        return;
    }
    __shared__ float sw[NREL * D];
    for (int i = threadIdx.x; i < NREL * D; i += blockDim.x) { float v = W[i]; sw[i] = v * v; }
    __syncthreads();
    int c = (blockIdx.x - Z) * 256 + threadIdx.x;
    if (c >= n_cat) return;
    const float4* row = reinterpret_cast<const float4*>(cat + (size_t)c * D);
    float c2[D];
#pragma unroll
    for (int i = 0; i < D / 4; i++) {
        float4 v = row[i];
        c2[4*i+0] = v.x*v.x; c2[4*i+1] = v.y*v.y; c2[4*i+2] = v.z*v.z; c2[4*i+3] = v.w*v.w;
    }
    float* out = g_S + (size_t)c * NREL;
#pragma unroll 4
    for (int r = 0; r < NREL; r++) {
        const float4* w4 = reinterpret_cast<const float4*>(sw + r * D);
        float acc = 0.f;
#pragma unroll
        for (int i = 0; i < D / 4; i++) {
            float4 w = w4[i];
            acc += c2[4*i+0]*w.x + c2[4*i+1]*w.y + c2[4*i+2]*w.z + c2[4*i+3]*w.w;
        }
        out[r] = acc;
    }
}

__global__ void k_hist(const int* __restrict__ head, const int* __restrict__ irow,
                       int E, int nnz, int n_cat) {
    int i = blockIdx.x * blockDim.x + threadIdx.x;
    if (i < E) atomicAdd(&g_cnt[head[i]], 1);
    else { int j = i - E; if (j < nnz) atomicAdd(&g_cnt[n_cat + irow[j]], 1); }
}

__global__ void k_scanA(int n) {
    __shared__ int s[1024];
    int tid = threadIdx.x;
    int i = blockIdx.x * 1024 + tid;
    int v = (i < n) ? g_cnt[i] : 0;
    s[tid] = v; __syncthreads();
    for (int o = 1; o < 1024; o <<= 1) {
        int t = (tid >= o) ? s[tid - o] : 0;
        __syncthreads();
        s[tid] += t;
        __syncthreads();
    }
    if (i < n) g_off[i] = s[tid] - v;
    if (tid == 1023) g_bsum[blockIdx.x] = s[1023];
}

__global__ void k_scanB(int nb, int n) {
    __shared__ int s[256];
    int tid = threadIdx.x;
    int v = (tid < nb) ? g_bsum[tid] : 0;
    s[tid] = v; __syncthreads();
    for (int o = 1; o < 256; o <<= 1) {
        int t = (tid >= o) ? s[tid - o] : 0;
        __syncthreads();
        s[tid] += t;
        __syncthreads();
    }
    if (tid < nb) g_bsum[tid] = s[tid] - v;
    if (tid == 255) g_off[n] = s[255];
}

__global__ void k_scanC(int n) {
    int i = blockIdx.x * 1024 + threadIdx.x;
    if (i < n) {
        int o = g_off[i] + g_bsum[blockIdx.x];
        g_off[i] = o;
        g_pos[i] = o;
    }
}

__global__ void k_sort(const int* __restrict__ head, const int* __restrict__ tail,
                       const int* __restrict__ et,
                       const int* __restrict__ irow, const int* __restrict__ icol,
                       const float* __restrict__ ival, int E, int nnz, int n_cat) {
    int i = blockIdx.x * blockDim.x + threadIdx.x;
    if (i < E) {
        int h = head[i];
        int p = atomicAdd(&g_pos[h], 1);
        g_pk[p] = tail[i] | ((et[i] - 1) << 17);
    } else {
        int j = i - E;
        if (j < nnz) {
            int r = irow[j];
            int p = atomicAdd(&g_pos[n_cat + r], 1) - E;
            g_uc[p] = icol[j];
            g_uv[p] = ival[j];
        }
    }
}

// fused persistent kernel: blocks [0,GA) do head aggregation; [GA,GA+GB) do user rows.
__global__ void __launch_bounds__(256) k_big(const float* __restrict__ cat,
                                             const float* __restrict__ ue,
                                             const float* __restrict__ W,
                                             float* __restrict__ agg,
                                             float* __restrict__ ua,
                                             int n_cat, int n_users, int E, int GA) {
    __shared__ float sw[NREL * D];       // W row-major
    __shared__ float swT[D * NREL];      // swT[d*32+r] = W[r,d] (uagg only)
    int warp = threadIdx.x >> 5, lane = threadIdx.x & 31;

    if ((int)blockIdx.x < GA) {
        // ---------------- head aggregation ----------------
        for (int i = threadIdx.x; i < NREL * D; i += blockDim.x) sw[i] = W[i];
        __syncthreads();
        int strideH = GA * 8;
        for (int h = blockIdx.x * 8 + warp; h < n_cat; h += strideH) {
            int beg = g_off[h], end = g_off[h + 1], len = end - beg;
            float* dst = agg + (size_t)h * D;
            float2* dst2 = reinterpret_cast<float2*>(dst);
            if (len == 0) { dst2[lane] = make_float2(0.f, 0.f); continue; }
            float Sh = g_S[(size_t)h * NREL + lane];
            float sum;
            unsigned long long acc = 0ull;

            if (len <= 32) {
                bool val = lane < len;
                int pk = val ? g_pk[beg + lane] : 0;
                int t = pk & 0x1FFFF, r = pk >> 17;
                float shr = __shfl_sync(FULL, Sh, r);
                float a = val ? shr * g_S[(size_t)t * NREL + r] : 0.f;
                float m = a;
#pragma unroll
                for (int o = 16; o > 0; o >>= 1) m = fmaxf(m, __shfl_xor_sync(FULL, m, o));
                float e = val ? __expf(a - m) : 0.f;
                sum = e;
#pragma unroll
                for (int o = 16; o > 0; o >>= 1) sum += __shfl_xor_sync(FULL, sum, o);
                int lenUp = (len + 3) & ~3;            // padded lanes: e=0, t=0 -> harmless
                for (int j = 0; j < lenUp; j += 4) {
#pragma unroll
                    for (int q = 0; q < 4; q++) {
                        float ej = __shfl_sync(FULL, e, j + q);
                        int pj = __shfl_sync(FULL, pk, j + q);
                        int tj = pj & 0x1FFFF, rj = pj >> 17;
                        if (((j + q) >= len)) { tj = 0; rj = 0; ej = 0.f; }
                        unsigned long long cw =
                            reinterpret_cast<const unsigned long long*>(cat + (size_t)tj * D)[lane];
                        unsigned long long ww =
                            reinterpret_cast<const unsigned long long*>(sw + rj * D)[lane];
                        unsigned long long ee, t1;
                        PACK2(ee, ej);
                        MULX2(t1, cw, ww);
                        FMAX2(acc, t1, ee, acc);
                    }
                }
            } else {
                // rare long-segment path
                float m = 0.f;
                for (int b = beg; b < end; b += 32) {
                    int i2 = b + lane;
                    int pk = (i2 < end) ? g_pk[i2] : 0;
                    int t = pk & 0x1FFFF, r = pk >> 17;
                    float shr = __shfl_sync(FULL, Sh, r);
                    if (i2 < end) m = fmaxf(m, shr * g_S[(size_t)t * NREL + r]);
                }
#pragma unroll
                for (int o = 16; o > 0; o >>= 1) m = fmaxf(m, __shfl_xor_sync(FULL, m, o));
                sum = 0.f;
                for (int b = beg; b < end; b += 32) {
                    int i2 = b + lane;
                    bool val = i2 < end;
                    int pk = val ? g_pk[i2] : 0;
                    int t = pk & 0x1FFFF, r = pk >> 17;
                    float shr = __shfl_sync(FULL, Sh, r);
                    float e = val ? __expf(shr * g_S[(size_t)t * NREL + r] - m) : 0.f;
                    sum += e;
                    int cnt = min(32, end - b);
                    for (int j = 0; j < cnt; j++) {
                        float ej = __shfl_sync(FULL, e, j);
                        int pj = __shfl_sync(FULL, pk, j);
                        int tj = pj & 0x1FFFF, rj = pj >> 17;
                        unsigned long long cw =
                            reinterpret_cast<const unsigned long long*>(cat + (size_t)tj * D)[lane];
                        unsigned long long ww =
                            reinterpret_cast<const unsigned long long*>(sw + rj * D)[lane];
                        unsigned long long ee, t1;
                        PACK2(ee, ej);
                        MULX2(t1, cw, ww);
                        FMAX2(acc, t1, ee, acc);
                    }
                }
#pragma unroll
                for (int o = 16; o > 0; o >>= 1) sum += __shfl_xor_sync(FULL, sum, o);
            }
            float ax, ay;
            UNPK2(ax, ay, acc);
            float inv = 1.f / sum;
            dst2[lane] = make_float2(ax * inv, ay * inv);
        }
    } else {
        // ---------------- user rows + gating ----------------
        for (int i = threadIdx.x; i < NREL * D; i += blockDim.x) {
            float v = W[i];
            sw[i] = v;
            int r = i / D, d = i % D;
            swT[d * NREL + r] = v;
        }
        __syncthreads();
        int GB = gridDim.x - GA;
        int strideU = GB * 8;
        for (int u = (blockIdx.x - GA) * 8 + warp; u < n_users; u += strideU) {
            int beg = g_off[n_cat + u] - E, end = g_off[n_cat + u + 1] - E;
            unsigned long long acc = 0ull;
            for (int b = beg; b < end; b += 32) {
                int i2 = b + lane;
                bool val = i2 < end;
                int c = val ? g_uc[i2] : 0;
                float v = val ? g_uv[i2] : 0.f;
                int cnt = min(32, end - b);
                int cntUp = (cnt + 3) & ~3;
                for (int j = 0; j < cntUp; j += 4) {
#pragma unroll
                    for (int q = 0; q < 4; q++) {
                        int cj = __shfl_sync(FULL, c, j + q);
                        float vj = __shfl_sync(FULL, v, j + q);
                        unsigned long long cw =
                            reinterpret_cast<const unsigned long long*>(cat + (size_t)cj * D)[lane];
                        unsigned long long vv;
                        PACK2(vv, vj);
                        FMAX2(acc, cw, vv, acc);
                    }
                }
            }
            // gating: score = softmax(ue[u] @ W^T); out = acc * (1 + score @ W)
            float u0 = ue[(size_t)u * D + lane];
            float u1 = ue[(size_t)u * D + 32 + lane];
            float logit = 0.f;
#pragma unroll
            for (int d = 0; d < 32; d++) {
                float ud = __shfl_sync(FULL, u0, d);
                logit += ud * swT[d * NREL + lane];
            }
#pragma unroll
            for (int d = 0; d < 32; d++) {
                float ud = __shfl_sync(FULL, u1, d);
                logit += ud * swT[(d + 32) * NREL + lane];
            }
            float mm = logit;
#pragma unroll
            for (int o = 16; o > 0; o >>= 1) mm = fmaxf(mm, __shfl_xor_sync(FULL, mm, o));
            float p = __expf(logit - mm);
            float s = p;
#pragma unroll
            for (int o = 16; o > 0; o >>= 1) s += __shfl_xor_sync(FULL, s, o);
            p /= s;
            float cx = 0.f, cy = 0.f;
#pragma unroll
            for (int r = 0; r < NREL; r++) {
                float pr = __shfl_sync(FULL, p, r);
                float2 w2 = reinterpret_cast<const float2*>(sw + r * D)[lane];
                cx += pr * w2.x;
                cy += pr * w2.y;
            }
            float ax, ay;
            UNPK2(ax, ay, acc);
            float2* ud2 = reinterpret_cast<float2*>(ua + (size_t)u * D);
            ud2[lane] = make_float2(ax * (1.f + cx), ay * (1.f + cy));
        }
    }
}

extern "C" void kernel_launch(void* const* d_in, const int* in_sizes, int n_in,
                              void* d_out, int out_size) {
    const float* cat = (const float*)d_in[0];
    const float* ue  = (const float*)d_in[1];
    const int*   ei  = (const int*)d_in[2];
    const int*   et  = (const int*)d_in[3];
    const int*   ir  = (const int*)d_in[4];
    const int*   ic  = (const int*)d_in[5];
    const float* iv  = (const float*)d_in[6];
    const float* W   = (const float*)d_in[7];

    int n_cat   = in_sizes[0] / D;
    int n_users = in_sizes[1] / D;
    int E       = in_sizes[3];
    int nnz     = in_sizes[6];

    const int* head = ei;
    const int* tail = ei + E;

    float* cat_agg  = (float*)d_out;
    float* user_agg = (float*)d_out + (size_t)n_cat * D;

    int n_tot = n_cat + n_users;
    int tot   = E + nnz;
    int nb    = (n_tot + 1023) / 1024;
    int Z     = (n_tot + 256) / 256;       // zero blocks (covers n_tot+1 entries)
    int SQ    = (n_cat + 255) / 256;

    const int GA = 1024, GB = 448;

    k_front<<<Z + SQ, 256>>>(cat, W, n_cat, n_tot, Z);
    k_hist<<<(tot + 255) / 256, 256>>>(head, ir, E, nnz, n_cat);
    k_scanA<<<nb, 1024>>>(n_tot);
    k_scanB<<<1, 256>>>(nb, n_tot);
    k_scanC<<<nb, 1024>>>(n_tot);
    k_sort<<<(tot + 255) / 256, 256>>>(head, tail, et, ir, ic, iv, E, nnz, n_cat);
    k_big<<<GA + GB, 256>>>(cat, ue, W, cat_agg, user_agg, n_cat, n_users, E, GA);
}

// round 6
// speedup vs baseline: 1.5133x; 1.0519x over previous
#include <cuda_runtime.h>
#include <cstdint>

#define D     64
#define NREL  32
#define MAXCAT  100000
#define MAXUSER 50000
#define MAXE    1600000
#define MAXNNZ  1000000
#define FULL 0xffffffffu

#define MULX2(o,a,b)   asm("mul.rn.f32x2 %0,%1,%2;"    : "=l"(o) : "l"(a), "l"(b))
#define FMAX2(o,a,b,c) asm("fma.rn.f32x2 %0,%1,%2,%3;" : "=l"(o) : "l"(a), "l"(b), "l"(c))
#define PACK2(o,x)     asm("mov.b64 %0,{%1,%1};"       : "=l"(o) : "f"(x))
#define UNPK2(x,y,i)   asm("mov.b64 {%0,%1},%2;"       : "=f"(x), "=f"(y) : "l"(i))

// ---- scratch ----
__device__ float g_S[(size_t)MAXCAT * NREL];
__device__ int   g_cnt[MAXCAT + MAXUSER + 2];
__device__ int   g_off[MAXCAT + MAXUSER + 2];
__device__ int   g_pos[MAXCAT + MAXUSER + 2];
__device__ int   g_bsum[256];
__device__ int   g_pk[MAXE];                       // tail | rel<<17, bucketed by head
__device__ int   g_uc[MAXNNZ];
__device__ float g_uv[MAXNNZ];

// fused: blocks [0,Z) zero the histogram; blocks [Z,Z+SQ) compute S
__global__ void k_front(const float* __restrict__ cat, const float* __restrict__ W,
                        int n_cat, int n_tot, int Z) {
    if ((int)blockIdx.x < Z) {
        int i = blockIdx.x * 256 + threadIdx.x;
        if (i <= n_tot) g_cnt[i] = 0;
        return;
    }
    __shared__ float sw[NREL * D];
    for (int i = threadIdx.x; i < NREL * D; i += blockDim.x) { float v = W[i]; sw[i] = v * v; }
    __syncthreads();
    int c = (blockIdx.x - Z) * 256 + threadIdx.x;
    if (c >= n_cat) return;
    const float4* row = reinterpret_cast<const float4*>(cat + (size_t)c * D);
    float c2[D];
#pragma unroll
    for (int i = 0; i < D / 4; i++) {
        float4 v = row[i];
        c2[4*i+0] = v.x*v.x; c2[4*i+1] = v.y*v.y; c2[4*i+2] = v.z*v.z; c2[4*i+3] = v.w*v.w;
    }
    float* out = g_S + (size_t)c * NREL;
#pragma unroll 4
    for (int r = 0; r < NREL; r++) {
        const float4* w4 = reinterpret_cast<const float4*>(sw + r * D);
        float acc = 0.f;
#pragma unroll
        for (int i = 0; i < D / 4; i++) {
            float4 w = w4[i];
            acc += c2[4*i+0]*w.x + c2[4*i+1]*w.y + c2[4*i+2]*w.z + c2[4*i+3]*w.w;
        }
        out[r] = acc;
    }
}

__global__ void k_hist(const int* __restrict__ head, const int* __restrict__ irow,
                       int E, int nnz, int n_cat) {
    int i = blockIdx.x * blockDim.x + threadIdx.x;
    if (i < E) atomicAdd(&g_cnt[head[i]], 1);
    else { int j = i - E; if (j < nnz) atomicAdd(&g_cnt[n_cat + irow[j]], 1); }
}

__global__ void k_scanA(int n) {
    __shared__ int s[1024];
    int tid = threadIdx.x;
    int i = blockIdx.x * 1024 + tid;
    int v = (i < n) ? g_cnt[i] : 0;
    s[tid] = v; __syncthreads();
    for (int o = 1; o < 1024; o <<= 1) {
        int t = (tid >= o) ? s[tid - o] : 0;
        __syncthreads();
        s[tid] += t;
        __syncthreads();
    }
    if (i < n) g_off[i] = s[tid] - v;
    if (tid == 1023) g_bsum[blockIdx.x] = s[1023];
}

__global__ void k_scanB(int nb, int n) {
    __shared__ int s[256];
    int tid = threadIdx.x;
    int v = (tid < nb) ? g_bsum[tid] : 0;
    s[tid] = v; __syncthreads();
    for (int o = 1; o < 256; o <<= 1) {
        int t = (tid >= o) ? s[tid - o] : 0;
        __syncthreads();
        s[tid] += t;
        __syncthreads();
    }
    if (tid < nb) g_bsum[tid] = s[tid] - v;
    if (tid == 255) g_off[n] = s[255];
}

__global__ void k_scanC(int n) {
    int i = blockIdx.x * 1024 + threadIdx.x;
    if (i < n) {
        int o = g_off[i] + g_bsum[blockIdx.x];
        g_off[i] = o;
        g_pos[i] = o;
    }
}

__global__ void k_sort(const int* __restrict__ head, const int* __restrict__ tail,
                       const int* __restrict__ et,
                       const int* __restrict__ irow, const int* __restrict__ icol,
                       const float* __restrict__ ival, int E, int nnz, int n_cat) {
    int i = blockIdx.x * blockDim.x + threadIdx.x;
    if (i < E) {
        int h = head[i];
        int p = atomicAdd(&g_pos[h], 1);
        g_pk[p] = tail[i] | ((et[i] - 1) << 17);
    } else {
        int j = i - E;
        if (j < nnz) {
            int r = irow[j];
            int p = atomicAdd(&g_pos[n_cat + r], 1) - E;
            g_uc[p] = icol[j];
            g_uv[p] = ival[j];
        }
    }
}

// fused persistent kernel: blocks [0,GA) aggregate heads; [GA,grid) aggregate users.
// Half-warp edge pairing: lanes 0-15 process edge j, lanes 16-31 edge j+1,
// each lane covering 16 bytes (float4) of the D=64 row.
__global__ void __launch_bounds__(256) k_big(const float* __restrict__ cat,
                                             const float* __restrict__ ue,
                                             const float* __restrict__ W,
                                             float* __restrict__ agg,
                                             float* __restrict__ ua,
                                             int n_cat, int n_users, int E, int GA) {
    __shared__ __align__(16) float sw[NREL * D];     // W row-major
    __shared__ float swT[D * NREL];                  // swT[d*32+r] = W[r,d] (user side)
    int warp = threadIdx.x >> 5, lane = threadIdx.x & 31;
    int half = lane >> 4;        // 0 or 1
    int l16  = lane & 15;

    if ((int)blockIdx.x < GA) {
        // ---------------- head aggregation ----------------
        for (int i = threadIdx.x; i < NREL * D; i += blockDim.x) sw[i] = W[i];
        __syncthreads();
        int strideH = GA * 8;
        for (int h = blockIdx.x * 8 + warp; h < n_cat; h += strideH) {
            int beg = g_off[h], end = g_off[h + 1], len = end - beg;
            float4* dst4 = reinterpret_cast<float4*>(agg + (size_t)h * D);
            if (len == 0) {
                if (lane < 16) dst4[lane] = make_float4(0.f, 0.f, 0.f, 0.f);
                continue;
            }
            float Sh = g_S[(size_t)h * NREL + lane];
            float sum;
            unsigned long long a01 = 0ull, a23 = 0ull;

            if (len <= 32) {
                bool val = lane < len;
                int pk = val ? g_pk[beg + lane] : 0;
                int t = pk & 0x1FFFF, r = pk >> 17;
                float shr = __shfl_sync(FULL, Sh, r);
                float a = val ? shr * g_S[(size_t)t * NREL + r] : 0.f;
                float m = a;
#pragma unroll
                for (int o = 16; o > 0; o >>= 1) m = fmaxf(m, __shfl_xor_sync(FULL, m, o));
                float e = val ? __expf(a - m) : 0.f;
                sum = e;
#pragma unroll
                for (int o = 16; o > 0; o >>= 1) sum += __shfl_xor_sync(FULL, sum, o);
                int lenUp = (len + 3) & ~3;      // padded lanes: e=0, t=0, r=0 -> harmless
                for (int j = 0; j < lenUp; j += 4) {
#pragma unroll
                    for (int q = 0; q < 4; q += 2) {
                        int src = j + q + half;
                        float ej = __shfl_sync(FULL, e, src);
                        int pj = __shfl_sync(FULL, pk, src);
                        int tj = pj & 0x1FFFF, rj = pj >> 17;
                        ulonglong2 cv = reinterpret_cast<const ulonglong2*>(cat + (size_t)tj * D)[l16];
                        ulonglong2 wv = reinterpret_cast<const ulonglong2*>(sw + rj * D)[l16];
                        unsigned long long ee, t1;
                        PACK2(ee, ej);
                        MULX2(t1, cv.x, wv.x); FMAX2(a01, t1, ee, a01);
                        MULX2(t1, cv.y, wv.y); FMAX2(a23, t1, ee, a23);
                    }
                }
            } else {
                float m = 0.f;
                for (int b = beg; b < end; b += 32) {
                    int i2 = b + lane;
                    int pk = (i2 < end) ? g_pk[i2] : 0;
                    int t = pk & 0x1FFFF, r = pk >> 17;
                    float shr = __shfl_sync(FULL, Sh, r);
                    if (i2 < end) m = fmaxf(m, shr * g_S[(size_t)t * NREL + r]);
                }
#pragma unroll
                for (int o = 16; o > 0; o >>= 1) m = fmaxf(m, __shfl_xor_sync(FULL, m, o));
                sum = 0.f;
                for (int b = beg; b < end; b += 32) {
                    int i2 = b + lane;
                    bool val = i2 < end;
                    int pk = val ? g_pk[i2] : 0;
                    int t = pk & 0x1FFFF, r = pk >> 17;
                    float shr = __shfl_sync(FULL, Sh, r);
                    float e = val ? __expf(shr * g_S[(size_t)t * NREL + r] - m) : 0.f;
                    sum += e;
                    int cnt = min(32, end - b);
                    int cntUp = (cnt + 3) & ~3;
                    for (int j = 0; j < cntUp; j += 4) {
#pragma unroll
                        for (int q = 0; q < 4; q += 2) {
                            int src = j + q + half;
                            float ej = __shfl_sync(FULL, e, src);
                            int pj = __shfl_sync(FULL, pk, src);
                            int tj = pj & 0x1FFFF, rj = pj >> 17;
                            ulonglong2 cv = reinterpret_cast<const ulonglong2*>(cat + (size_t)tj * D)[l16];
                            ulonglong2 wv = reinterpret_cast<const ulonglong2*>(sw + rj * D)[l16];
                            unsigned long long ee, t1;
                            PACK2(ee, ej);
                            MULX2(t1, cv.x, wv.x); FMAX2(a01, t1, ee, a01);
                            MULX2(t1, cv.y, wv.y); FMAX2(a23, t1, ee, a23);
                        }
                    }
                }
#pragma unroll
                for (int o = 16; o > 0; o >>= 1) sum += __shfl_xor_sync(FULL, sum, o);
            }
            float x0, x1, x2, x3;
            UNPK2(x0, x1, a01);
            UNPK2(x2, x3, a23);
            x0 += __shfl_xor_sync(FULL, x0, 16);
            x1 += __shfl_xor_sync(FULL, x1, 16);
            x2 += __shfl_xor_sync(FULL, x2, 16);
            x3 += __shfl_xor_sync(FULL, x3, 16);
            float inv = 1.f / sum;
            if (lane < 16)
                dst4[lane] = make_float4(x0 * inv, x1 * inv, x2 * inv, x3 * inv);
        }
    } else {
        // ---------------- user rows + gating ----------------
        for (int i = threadIdx.x; i < NREL * D; i += blockDim.x) {
            float v = W[i];
            sw[i] = v;
            int r = i / D, d = i % D;
            swT[d * NREL + r] = v;
        }
        __syncthreads();
        int GB = gridDim.x - GA;
        int strideU = GB * 8;
        for (int u = (blockIdx.x - GA) * 8 + warp; u < n_users; u += strideU) {
            int beg = g_off[n_cat + u] - E, end = g_off[n_cat + u + 1] - E;
            unsigned long long a01 = 0ull, a23 = 0ull;
            for (int b = beg; b < end; b += 32) {
                int i2 = b + lane;
                bool val = i2 < end;
                int c = val ? g_uc[i2] : 0;
                float v = val ? g_uv[i2] : 0.f;
                int cnt = min(32, end - b);
                int cntUp = (cnt + 3) & ~3;
                for (int j = 0; j < cntUp; j += 4) {
#pragma unroll
                    for (int q = 0; q < 4; q += 2) {
                        int src = j + q + half;
                        int cj = __shfl_sync(FULL, c, src);
                        float vj = __shfl_sync(FULL, v, src);
                        ulonglong2 cv = reinterpret_cast<const ulonglong2*>(cat + (size_t)cj * D)[l16];
                        unsigned long long vv;
                        PACK2(vv, vj);
                        FMAX2(a01, cv.x, vv, a01);
                        FMAX2(a23, cv.y, vv, a23);
                    }
                }
            }
            float x0, x1, x2, x3;
            UNPK2(x0, x1, a01);
            UNPK2(x2, x3, a23);
            x0 += __shfl_xor_sync(FULL, x0, 16);
            x1 += __shfl_xor_sync(FULL, x1, 16);
            x2 += __shfl_xor_sync(FULL, x2, 16);
            x3 += __shfl_xor_sync(FULL, x3, 16);
            // redistribute float4@lane<16 -> float2 per lane (dims 2*lane, 2*lane+1)
            float v0 = __shfl_sync(FULL, x0, lane >> 1);
            float v1 = __shfl_sync(FULL, x1, lane >> 1);
            float v2 = __shfl_sync(FULL, x2, lane >> 1);
            float v3 = __shfl_sync(FULL, x3, lane >> 1);
            float ax = (lane & 1) ? v2 : v0;
            float ay = (lane & 1) ? v3 : v1;
            // gating: score = softmax(ue[u] @ W^T); out = acc * (1 + score @ W)
            float u0 = ue[(size_t)u * D + lane];
            float u1 = ue[(size_t)u * D + 32 + lane];
            float logit = 0.f;
#pragma unroll
            for (int d = 0; d < 32; d++) {
                float ud = __shfl_sync(FULL, u0, d);
                logit += ud * swT[d * NREL + lane];
            }
#pragma unroll
            for (int d = 0; d < 32; d++) {
                float ud = __shfl_sync(FULL, u1, d);
                logit += ud * swT[(d + 32) * NREL + lane];
            }
            float mm = logit;
#pragma unroll
            for (int o = 16; o > 0; o >>= 1) mm = fmaxf(mm, __shfl_xor_sync(FULL, mm, o));
            float p = __expf(logit - mm);
            float s = p;
#pragma unroll
            for (int o = 16; o > 0; o >>= 1) s += __shfl_xor_sync(FULL, s, o);
            p /= s;
            float cx = 0.f, cy = 0.f;
#pragma unroll
            for (int r = 0; r < NREL; r++) {
                float pr = __shfl_sync(FULL, p, r);
                float2 w2 = reinterpret_cast<const float2*>(sw + r * D)[lane];
                cx += pr * w2.x;
                cy += pr * w2.y;
            }
            float2* ud2 = reinterpret_cast<float2*>(ua + (size_t)u * D);
            ud2[lane] = make_float2(ax * (1.f + cx), ay * (1.f + cy));
        }
    }
}

extern "C" void kernel_launch(void* const* d_in, const int* in_sizes, int n_in,
                              void* d_out, int out_size) {
    const float* cat = (const float*)d_in[0];
    const float* ue  = (const float*)d_in[1];
    const int*   ei  = (const int*)d_in[2];
    const int*   et  = (const int*)d_in[3];
    const int*   ir  = (const int*)d_in[4];
    const int*   ic  = (const int*)d_in[5];
    const float* iv  = (const float*)d_in[6];
    const float* W   = (const float*)d_in[7];

    int n_cat   = in_sizes[0] / D;
    int n_users = in_sizes[1] / D;
    int E       = in_sizes[3];
    int nnz     = in_sizes[6];

    const int* head = ei;
    const int* tail = ei + E;

    float* cat_agg  = (float*)d_out;
    float* user_agg = (float*)d_out + (size_t)n_cat * D;

    int n_tot = n_cat + n_users;
    int tot   = E + nnz;
    int nb    = (n_tot + 1023) / 1024;
    int Z     = (n_tot + 256) / 256;
    int SQ    = (n_cat + 255) / 256;

    const int GA = 824, GB = 360;   // GA+GB = 1184 = 148 SMs * 8 blocks

    k_front<<<Z + SQ, 256>>>(cat, W, n_cat, n_tot, Z);
    k_hist<<<(tot + 255) / 256, 256>>>(head, ir, E, nnz, n_cat);
    k_scanA<<<nb, 1024>>>(n_tot);
    k_scanB<<<1, 256>>>(nb, n_tot);
    k_scanC<<<nb, 1024>>>(n_tot);
    k_sort<<<(tot + 255) / 256, 256>>>(head, tail, et, ir, ic, iv, E, nnz, n_cat);
    k_big<<<GA + GB, 256>>>(cat, ue, W, cat_agg, user_agg, n_cat, n_users, E, GA);
}

// round 7
// speedup vs baseline: 1.6502x; 1.0905x over previous
#include <cuda_runtime.h>
#include <cstdint>

#define D     64
#define NREL  32
#define MAXCAT  100000
#define MAXUSER 50000
#define MAXE    1600000
#define MAXNNZ  1000000
#define FULL 0xffffffffu

#define MULX2(o,a,b)   asm("mul.rn.f32x2 %0,%1,%2;"    : "=l"(o) : "l"(a), "l"(b))
#define FMAX2(o,a,b,c) asm("fma.rn.f32x2 %0,%1,%2,%3;" : "=l"(o) : "l"(a), "l"(b), "l"(c))
#define PACK2(o,x)     asm("mov.b64 %0,{%1,%1};"       : "=l"(o) : "f"(x))
#define UNPK2(x,y,i)   asm("mov.b64 {%0,%1},%2;"       : "=f"(x), "=f"(y) : "l"(i))

// ---- scratch ----
__device__ float g_S[(size_t)MAXCAT * NREL];
__device__ int   g_cnt[MAXCAT + MAXUSER + 2];
__device__ int   g_off[MAXCAT + MAXUSER + 2];
__device__ int   g_pos[MAXCAT + MAXUSER + 2];
__device__ int   g_bsum[256];
__device__ int2  g_pk2[MAXE];                     // {tail|rel<<17, att bits}, bucketed by head
__device__ unsigned long long g_up[MAXNNZ];       // col | val<<32, bucketed by user row

// fused: blocks [0,Z) zero the histogram; blocks [Z,Z+SQ) compute S
__global__ void k_front(const float* __restrict__ cat, const float* __restrict__ W,
                        int n_cat, int n_tot, int Z) {
    if ((int)blockIdx.x < Z) {
        int i = blockIdx.x * 256 + threadIdx.x;
        if (i <= n_tot) g_cnt[i] = 0;
        return;
    }
    __shared__ float sw[NREL * D];
    for (int i = threadIdx.x; i < NREL * D; i += blockDim.x) { float v = W[i]; sw[i] = v * v; }
    __syncthreads();
    int c = (blockIdx.x - Z) * 256 + threadIdx.x;
    if (c >= n_cat) return;
    const float4* row = reinterpret_cast<const float4*>(cat + (size_t)c * D);
    float c2[D];
#pragma unroll
    for (int i = 0; i < D / 4; i++) {
        float4 v = row[i];
        c2[4*i+0] = v.x*v.x; c2[4*i+1] = v.y*v.y; c2[4*i+2] = v.z*v.z; c2[4*i+3] = v.w*v.w;
    }
    float* out = g_S + (size_t)c * NREL;
#pragma unroll 4
    for (int r = 0; r < NREL; r++) {
        const float4* w4 = reinterpret_cast<const float4*>(sw + r * D);
        float acc = 0.f;
#pragma unroll
        for (int i = 0; i < D / 4; i++) {
            float4 w = w4[i];
            acc += c2[4*i+0]*w.x + c2[4*i+1]*w.y + c2[4*i+2]*w.z + c2[4*i+3]*w.w;
        }
        out[r] = acc;
    }
}

__global__ void k_hist(const int* __restrict__ head, const int* __restrict__ irow,
                       int E, int nnz, int n_cat) {
    int i = blockIdx.x * blockDim.x + threadIdx.x;
    if (i < E) atomicAdd(&g_cnt[head[i]], 1);
    else { int j = i - E; if (j < nnz) atomicAdd(&g_cnt[n_cat + irow[j]], 1); }
}

__global__ void k_scanA(int n) {
    __shared__ int s[1024];
    int tid = threadIdx.x;
    int i = blockIdx.x * 1024 + tid;
    int v = (i < n) ? g_cnt[i] : 0;
    s[tid] = v; __syncthreads();
    for (int o = 1; o < 1024; o <<= 1) {
        int t = (tid >= o) ? s[tid - o] : 0;
        __syncthreads();
        s[tid] += t;
        __syncthreads();
    }
    if (i < n) g_off[i] = s[tid] - v;
    if (tid == 1023) g_bsum[blockIdx.x] = s[1023];
}

__global__ void k_scanB(int nb, int n) {
    __shared__ int s[256];
    int tid = threadIdx.x;
    int v = (tid < nb) ? g_bsum[tid] : 0;
    s[tid] = v; __syncthreads();
    for (int o = 1; o < 256; o <<= 1) {
        int t = (tid >= o) ? s[tid - o] : 0;
        __syncthreads();
        s[tid] += t;
        __syncthreads();
    }
    if (tid < nb) g_bsum[tid] = s[tid] - v;
    if (tid == 255) g_off[n] = s[255];
}

__global__ void k_scanC(int n) {
    int i = blockIdx.x * 1024 + threadIdx.x;
    if (i < n) {
        int o = g_off[i] + g_bsum[blockIdx.x];
        g_off[i] = o;
        g_pos[i] = o;
    }
}

// bucket-scatter; edge side also precomputes att = S[h,r]*S[t,r] (absorbs scattered
// S gathers here, where one-thread-per-edge TLP hides the latency).
__global__ void k_sort(const int* __restrict__ head, const int* __restrict__ tail,
                       const int* __restrict__ et,
                       const int* __restrict__ irow, const int* __restrict__ icol,
                       const float* __restrict__ ival, int E, int nnz, int n_cat) {
    int i = blockIdx.x * blockDim.x + threadIdx.x;
    if (i < E) {
        int h = head[i], t = tail[i], r = et[i] - 1;
        float att = g_S[(size_t)h * NREL + r] * g_S[(size_t)t * NREL + r];
        int p = atomicAdd(&g_pos[h], 1);
        g_pk2[p] = make_int2(t | (r << 17), __float_as_int(att));
    } else {
        int j = i - E;
        if (j < nnz) {
            int r = irow[j];
            int p = atomicAdd(&g_pos[n_cat + r], 1) - E;
            g_up[p] = (unsigned int)icol[j] |
                      ((unsigned long long)__float_as_uint(ival[j]) << 32);
        }
    }
}

// persistent fused kernel: blocks [0,GA) heads (online softmax agg); rest users.
// Half-warp edge pairing (16 lanes/edge, float4 per lane), 8 edges in flight.
__global__ void __launch_bounds__(256, 6) k_big(const float* __restrict__ cat,
                                                const float* __restrict__ ue,
                                                const float* __restrict__ W,
                                                float* __restrict__ agg,
                                                float* __restrict__ ua,
                                                int n_cat, int n_users, int E, int GA) {
    __shared__ __align__(16) float sw[NREL * D];     // W row-major
    __shared__ float swT[D * NREL];                  // swT[d*32+r] = W[r,d] (user side)
    int warp = threadIdx.x >> 5, lane = threadIdx.x & 31;
    int half = lane >> 4;
    int l16  = lane & 15;

    if ((int)blockIdx.x < GA) {
        // ---------------- head aggregation (online softmax) ----------------
        for (int i = threadIdx.x; i < NREL * D; i += blockDim.x) sw[i] = W[i];
        __syncthreads();
        int strideH = GA * 8;
        for (int h = blockIdx.x * 8 + warp; h < n_cat; h += strideH) {
            int beg = g_off[h], end = g_off[h + 1];
            float4* dst4 = reinterpret_cast<float4*>(agg + (size_t)h * D);
            if (beg == end) {
                if (lane < 16) dst4[lane] = make_float4(0.f, 0.f, 0.f, 0.f);
                continue;
            }
            float m = 0.f, sum = 0.f;                  // att >= 0
            unsigned long long a01 = 0ull, a23 = 0ull;
            for (int b = beg; b < end; b += 32) {
                int i2 = b + lane;
                bool val = i2 < end;
                int2 pa = val ? g_pk2[i2] : make_int2(0, 0);
                float a = val ? __int_as_float(pa.y) : 0.f;
                int mi;
                asm("redux.sync.max.s32 %0, %1, 0xffffffff;" : "=r"(mi) : "r"(__float_as_int(a)));
                float mnew = fmaxf(m, __int_as_float(mi));
                float scale = __expf(m - mnew);
                m = mnew;
                float e = val ? __expf(a - mnew) : 0.f;
                float cs = e;
#pragma unroll
                for (int o = 16; o > 0; o >>= 1) cs += __shfl_xor_sync(FULL, cs, o);
                sum = sum * scale + cs;
                unsigned long long sc2;
                PACK2(sc2, scale);
                MULX2(a01, a01, sc2);
                MULX2(a23, a23, sc2);
                int cnt = min(32, end - b);
                int cntUp = (cnt + 7) & ~7;            // lanes >= cnt have e=0, pk=0 -> harmless
                for (int j = 0; j < cntUp; j += 8) {
#pragma unroll
                    for (int q = 0; q < 8; q += 2) {
                        int src = j + q + half;
                        float ej = __shfl_sync(FULL, e, src);
                        int pj = __shfl_sync(FULL, pa.x, src);
                        int tj = pj & 0x1FFFF, rj = pj >> 17;
                        ulonglong2 cv = reinterpret_cast<const ulonglong2*>(cat + (size_t)tj * D)[l16];
                        ulonglong2 wv = reinterpret_cast<const ulonglong2*>(sw + rj * D)[l16];
                        unsigned long long ee, t1;
                        PACK2(ee, ej);
                        MULX2(t1, cv.x, wv.x); FMAX2(a01, t1, ee, a01);
                        MULX2(t1, cv.y, wv.y); FMAX2(a23, t1, ee, a23);
                    }
                }
            }
            float x0, x1, x2, x3;
            UNPK2(x0, x1, a01);
            UNPK2(x2, x3, a23);
            x0 += __shfl_xor_sync(FULL, x0, 16);
            x1 += __shfl_xor_sync(FULL, x1, 16);
            x2 += __shfl_xor_sync(FULL, x2, 16);
            x3 += __shfl_xor_sync(FULL, x3, 16);
            float inv = 1.f / sum;
            if (lane < 16)
                dst4[lane] = make_float4(x0 * inv, x1 * inv, x2 * inv, x3 * inv);
        }
    } else {
        // ---------------- user rows + gating ----------------
        for (int i = threadIdx.x; i < NREL * D; i += blockDim.x) {
            float v = W[i];
            sw[i] = v;
            int r = i / D, d = i % D;
            swT[d * NREL + r] = v;
        }
        __syncthreads();
        int GB = gridDim.x - GA;
        int strideU = GB * 8;
        for (int u = (blockIdx.x - GA) * 8 + warp; u < n_users; u += strideU) {
            int beg = g_off[n_cat + u] - E, end = g_off[n_cat + u + 1] - E;
            unsigned long long a01 = 0ull, a23 = 0ull;
            for (int b = beg; b < end; b += 32) {
                int i2 = b + lane;
                bool val = i2 < end;
                unsigned long long cvp = val ? g_up[i2] : 0ull;
                int c = (int)(unsigned int)cvp;
                float v = val ? __uint_as_float((unsigned int)(cvp >> 32)) : 0.f;
                int cnt = min(32, end - b);
                int cntUp = (cnt + 7) & ~7;
                for (int j = 0; j < cntUp; j += 8) {
#pragma unroll
                    for (int q = 0; q < 8; q += 2) {
                        int src = j + q + half;
                        int cj = __shfl_sync(FULL, c, src);
                        float vj = __shfl_sync(FULL, v, src);
                        ulonglong2 cv = reinterpret_cast<const ulonglong2*>(cat + (size_t)cj * D)[l16];
                        unsigned long long vv;
                        PACK2(vv, vj);
                        FMAX2(a01, cv.x, vv, a01);
                        FMAX2(a23, cv.y, vv, a23);
                    }
                }
            }
            float x0, x1, x2, x3;
            UNPK2(x0, x1, a01);
            UNPK2(x2, x3, a23);
            x0 += __shfl_xor_sync(FULL, x0, 16);
            x1 += __shfl_xor_sync(FULL, x1, 16);
            x2 += __shfl_xor_sync(FULL, x2, 16);
            x3 += __shfl_xor_sync(FULL, x3, 16);
            // redistribute float4@lane<16 -> float2 per lane (dims 2*lane, 2*lane+1)
            float v0 = __shfl_sync(FULL, x0, lane >> 1);
            float v1 = __shfl_sync(FULL, x1, lane >> 1);
            float v2 = __shfl_sync(FULL, x2, lane >> 1);
            float v3 = __shfl_sync(FULL, x3, lane >> 1);
            float ax = (lane & 1) ? v2 : v0;
            float ay = (lane & 1) ? v3 : v1;
            // gating: score = softmax(ue[u] @ W^T); out = acc * (1 + score @ W)
            float u0 = ue[(size_t)u * D + lane];
            float u1 = ue[(size_t)u * D + 32 + lane];
            float logit = 0.f;
#pragma unroll
            for (int d = 0; d < 32; d++) {
                float ud = __shfl_sync(FULL, u0, d);
                logit += ud * swT[d * NREL + lane];
            }
#pragma unroll
            for (int d = 0; d < 32; d++) {
                float ud = __shfl_sync(FULL, u1, d);
                logit += ud * swT[(d + 32) * NREL + lane];
            }
            float mm = logit;
#pragma unroll
            for (int o = 16; o > 0; o >>= 1) mm = fmaxf(mm, __shfl_xor_sync(FULL, mm, o));
            float p = __expf(logit - mm);
            float s = p;
#pragma unroll
            for (int o = 16; o > 0; o >>= 1) s += __shfl_xor_sync(FULL, s, o);
            p /= s;
            float cx = 0.f, cy = 0.f;
#pragma unroll
            for (int r = 0; r < NREL; r++) {
                float pr = __shfl_sync(FULL, p, r);
                float2 w2 = reinterpret_cast<const float2*>(sw + r * D)[lane];
                cx += pr * w2.x;
                cy += pr * w2.y;
            }
            float2* ud2 = reinterpret_cast<float2*>(ua + (size_t)u * D);
            ud2[lane] = make_float2(ax * (1.f + cx), ay * (1.f + cy));
        }
    }
}

extern "C" void kernel_launch(void* const* d_in, const int* in_sizes, int n_in,
                              void* d_out, int out_size) {
    const float* cat = (const float*)d_in[0];
    const float* ue  = (const float*)d_in[1];
    const int*   ei  = (const int*)d_in[2];
    const int*   et  = (const int*)d_in[3];
    const int*   ir  = (const int*)d_in[4];
    const int*   ic  = (const int*)d_in[5];
    const float* iv  = (const float*)d_in[6];
    const float* W   = (const float*)d_in[7];

    int n_cat   = in_sizes[0] / D;
    int n_users = in_sizes[1] / D;
    int E       = in_sizes[3];
    int nnz     = in_sizes[6];

    const int* head = ei;
    const int* tail = ei + E;

    float* cat_agg  = (float*)d_out;
    float* user_agg = (float*)d_out + (size_t)n_cat * D;

    int n_tot = n_cat + n_users;
    int tot   = E + nnz;
    int nb    = (n_tot + 1023) / 1024;
    int Z     = (n_tot + 256) / 256;
    int SQ    = (n_cat + 255) / 256;

    const int GA = 612, GB = 276;   // GA+GB = 888 = 148 SMs * 6 blocks

    k_front<<<Z + SQ, 256>>>(cat, W, n_cat, n_tot, Z);
    k_hist<<<(tot + 255) / 256, 256>>>(head, ir, E, nnz, n_cat);
    k_scanA<<<nb, 1024>>>(n_tot);
    k_scanB<<<1, 256>>>(nb, n_tot);
    k_scanC<<<nb, 1024>>>(n_tot);
    k_sort<<<(tot + 255) / 256, 256>>>(head, tail, et, ir, ic, iv, E, nnz, n_cat);
    k_big<<<GA + GB, 256>>>(cat, ue, W, cat_agg, user_agg, n_cat, n_users, E, GA);
}